// round 13
// baseline (speedup 1.0000x reference)
#include <cuda_runtime.h>
#include <math.h>

#define N_ROWS 12288
#define D      128
#define KSPLIT 6          // K chunk = 2048
#define TM     64
#define TK     16
#define RPB    16         // rows per block in epilogue

// ---------------- scratch (static __device__ -> allowed) ----------------
__device__ float d_xnorm[(size_t)N_ROWS * D];            // 6.3 MB
__device__ float d_xg[(size_t)N_ROWS * D];               // 6.3 MB (gate[j] * x_norm[j])
__device__ float d_gate[N_ROWS];
__device__ int   d_selRows[N_ROWS];
__device__ int   d_count;
__device__ float d_partial[KSPLIT][(size_t)N_ROWS * D];  // 37.7 MB split-K partials

__global__ void reset_kernel() { d_count = 0; }

// ---------------- kernel 1: LN_in + logits + gumbel gate + xg ----------------
__global__ __launch_bounds__(128) void prep_kernel(
    const float* __restrict__ x, const float* __restrict__ u,
    const float* __restrict__ Wn, const float* __restrict__ bn,
    const float* __restrict__ g_in, const float* __restrict__ b_in)
{
    const int row = blockIdx.x;
    const int d = threadIdx.x;
    const int w = d >> 5, l = d & 31;

    float v = x[(size_t)row * D + d];
    float s = v, sq = v * v;
    #pragma unroll
    for (int o = 16; o; o >>= 1) {
        s  += __shfl_xor_sync(0xffffffffu, s, o);
        sq += __shfl_xor_sync(0xffffffffu, sq, o);
    }
    __shared__ float sm[4][4];
    if (l == 0) { sm[0][w] = s; sm[1][w] = sq; }
    __syncthreads();
    s  = sm[0][0] + sm[0][1] + sm[0][2] + sm[0][3];
    sq = sm[1][0] + sm[1][1] + sm[1][2] + sm[1][3];
    float mean = s * (1.f / 128.f);
    float var  = sq * (1.f / 128.f) - mean * mean;
    float xn = (v - mean) * rsqrtf(var + 1e-5f) * g_in[d] + b_in[d];
    d_xnorm[(size_t)row * D + d] = xn;

    // logits = x_norm @ Wn  (Wn is [D,2] row-major)
    float p0 = xn * Wn[d * 2 + 0];
    float p1 = xn * Wn[d * 2 + 1];
    #pragma unroll
    for (int o = 16; o; o >>= 1) {
        p0 += __shfl_xor_sync(0xffffffffu, p0, o);
        p1 += __shfl_xor_sync(0xffffffffu, p1, o);
    }
    if (l == 0) { sm[2][w] = p0; sm[3][w] = p1; }
    __syncthreads();
    p0 = sm[2][0] + sm[2][1] + sm[2][2] + sm[2][3] + bn[0];
    p1 = sm[3][0] + sm[3][1] + sm[3][2] + sm[3][3] + bn[1];

    float u0 = fminf(fmaxf(u[(size_t)row * 2 + 0], 1e-10f), 1.0f);
    float u1 = fminf(fmaxf(u[(size_t)row * 2 + 1], 1e-10f), 1.0f);
    float gu0 = -logf(-logf(u0) + 1e-10f);
    float gu1 = -logf(-logf(u1) + 1e-10f);
    // argmax of softmax((logits+gumbel)/TAU) == argmax(logits+gumbel); ties -> idx 0
    float gate = ((p1 + gu1) > (p0 + gu0)) ? 1.0f : 0.0f;

    if (d == 0) {
        d_gate[row] = gate;
        if (gate > 0.5f) {
            int pos = atomicAdd(&d_count, 1);
            d_selRows[pos] = row;
        }
    }
    d_xg[(size_t)row * D + d] = xn * gate;
}

// ---------------- kernel 2: view2_partial = adj[sel,:Kslice] @ xg ----------------
// Tile: TM=64 rows x D=128 cols x TK=16, 256 threads, each thread 4x8 outputs.
__global__ __launch_bounds__(256) void gemm_kernel(const float* __restrict__ adj)
{
    const int count = d_count;
    const int mtile = blockIdx.x;
    if (mtile * TM >= count) return;
    const int ks = blockIdx.y;
    const int KC = N_ROWS / KSPLIT;   // 2048
    const int k0 = ks * KC;

    __shared__ float As[TK][TM];   // transposed A tile
    __shared__ float Bs[TK][D];

    const int tid = threadIdx.x;

    // A-load mapping: 64 rows x 16 k, one float4 per thread
    const int lr = tid >> 2;                 // 0..63
    const int lc = (tid & 3) * 4;            // 0,4,8,12
    const int grow = mtile * TM + lr;
    const int arow = (grow < count) ? d_selRows[grow] : d_selRows[count - 1];
    const float* aptr = adj + (size_t)arow * N_ROWS + k0 + lc;

    // B-load mapping: 16 rows x 128 cols, two float4 per thread
    const int brow = tid >> 5;               // 0..7 (+8)
    const int bcol = (tid & 31) * 4;         // 0..124
    const float* bptr = d_xg + (size_t)(k0 + brow) * D + bcol;

    float acc[4][8];
    #pragma unroll
    for (int i = 0; i < 4; i++)
        #pragma unroll
        for (int j = 0; j < 8; j++) acc[i][j] = 0.f;

    const int ty4 = (tid >> 4) * 4;   // output row base within tile
    const int tx8 = (tid & 15) * 8;   // output col base

    for (int kb = 0; kb < KC; kb += TK) {
        float4 a4  = *reinterpret_cast<const float4*>(aptr + kb);
        float4 b4a = *reinterpret_cast<const float4*>(bptr + (size_t)kb * D);
        float4 b4b = *reinterpret_cast<const float4*>(bptr + (size_t)(kb + 8) * D);
        __syncthreads();
        As[lc + 0][lr] = a4.x;
        As[lc + 1][lr] = a4.y;
        As[lc + 2][lr] = a4.z;
        As[lc + 3][lr] = a4.w;
        *reinterpret_cast<float4*>(&Bs[brow][bcol])     = b4a;
        *reinterpret_cast<float4*>(&Bs[brow + 8][bcol]) = b4b;
        __syncthreads();
        #pragma unroll
        for (int kk = 0; kk < TK; kk++) {
            float4 av  = *reinterpret_cast<const float4*>(&As[kk][ty4]);
            float4 bv0 = *reinterpret_cast<const float4*>(&Bs[kk][tx8]);
            float4 bv1 = *reinterpret_cast<const float4*>(&Bs[kk][tx8 + 4]);
            float a[4] = {av.x, av.y, av.z, av.w};
            float b[8] = {bv0.x, bv0.y, bv0.z, bv0.w, bv1.x, bv1.y, bv1.z, bv1.w};
            #pragma unroll
            for (int i = 0; i < 4; i++)
                #pragma unroll
                for (int j = 0; j < 8; j++)
                    acc[i][j] += a[i] * b[j];
        }
    }

    float* pbase = d_partial[ks];
    #pragma unroll
    for (int i = 0; i < 4; i++) {
        int gr = mtile * TM + ty4 + i;
        if (gr < count) {
            int orow = d_selRows[gr];
            float* p = pbase + (size_t)orow * D + tx8;
            *reinterpret_cast<float4*>(p)     = make_float4(acc[i][0], acc[i][1], acc[i][2], acc[i][3]);
            *reinterpret_cast<float4*>(p + 4) = make_float4(acc[i][4], acc[i][5], acc[i][6], acc[i][7]);
        }
    }
}

// ---------------- kernel 3: per-row matmuls + sigmoid fuse + residual + LN_out ----
__global__ __launch_bounds__(128) void epilogue_kernel(
    const float* __restrict__ x,
    const float* __restrict__ W1, const float* __restrict__ b1,
    const float* __restrict__ W2, const float* __restrict__ b2,
    const float* __restrict__ Wg, const float* __restrict__ bg,
    const float* __restrict__ g_out, const float* __restrict__ b_out,
    float* __restrict__ out)
{
    const int rb = blockIdx.x * RPB;
    const int d = threadIdx.x;

    __shared__ float xn_s[RPB][D];
    __shared__ float v2_s[RPB][D];

    #pragma unroll
    for (int r = 0; r < RPB; r++) {
        int row = rb + r;
        xn_s[r][d] = d_xnorm[(size_t)row * D + d];
        float v2 = 0.f;
        if (d_gate[row] > 0.5f) {
            #pragma unroll
            for (int ks = 0; ks < KSPLIT; ks++)
                v2 += d_partial[ks][(size_t)row * D + d];
        }
        v2_s[r][d] = v2;
    }
    __syncthreads();

    float acc1[RPB], acc2[RPB], accg[RPB];
    #pragma unroll
    for (int r = 0; r < RPB; r++) { acc1[r] = 0.f; acc2[r] = 0.f; accg[r] = 0.f; }

    // h1 = xn@W1, h2 = v2@W2, g = xn@Wg[:D] + v2@Wg[D:]
    for (int k = 0; k < D; k += 4) {
        float w1_0 = W1[(k + 0) * D + d], w1_1 = W1[(k + 1) * D + d];
        float w1_2 = W1[(k + 2) * D + d], w1_3 = W1[(k + 3) * D + d];
        float w2_0 = W2[(k + 0) * D + d], w2_1 = W2[(k + 1) * D + d];
        float w2_2 = W2[(k + 2) * D + d], w2_3 = W2[(k + 3) * D + d];
        float wg_0 = Wg[(k + 0) * D + d], wg_1 = Wg[(k + 1) * D + d];
        float wg_2 = Wg[(k + 2) * D + d], wg_3 = Wg[(k + 3) * D + d];
        #pragma unroll
        for (int r = 0; r < RPB; r++) {
            float4 xv = *reinterpret_cast<const float4*>(&xn_s[r][k]);
            float4 vv = *reinterpret_cast<const float4*>(&v2_s[r][k]);
            acc1[r] += xv.x * w1_0; acc1[r] += xv.y * w1_1;
            acc1[r] += xv.z * w1_2; acc1[r] += xv.w * w1_3;
            accg[r] += xv.x * wg_0; accg[r] += xv.y * wg_1;
            accg[r] += xv.z * wg_2; accg[r] += xv.w * wg_3;
            acc2[r] += vv.x * w2_0; acc2[r] += vv.y * w2_1;
            acc2[r] += vv.z * w2_2; acc2[r] += vv.w * w2_3;
        }
    }
    for (int k = 0; k < D; k += 4) {
        float wg_0 = Wg[(D + k + 0) * D + d], wg_1 = Wg[(D + k + 1) * D + d];
        float wg_2 = Wg[(D + k + 2) * D + d], wg_3 = Wg[(D + k + 3) * D + d];
        #pragma unroll
        for (int r = 0; r < RPB; r++) {
            float4 vv = *reinterpret_cast<const float4*>(&v2_s[r][k]);
            accg[r] += vv.x * wg_0; accg[r] += vv.y * wg_1;
            accg[r] += vv.z * wg_2; accg[r] += vv.w * wg_3;
        }
    }

    float b1d = b1[d], b2d = b2[d], bgd = bg[d];
    __syncthreads();   // done reading xn_s/v2_s, about to overwrite xn_s
    #pragma unroll
    for (int r = 0; r < RPB; r++) {
        float sg = accg[r] + bgd;
        float s1 = 1.f / (1.f + expf(-sg));
        float f = s1 * (acc1[r] + b1d) + (1.f - s1) * (acc2[r] + b2d)
                + x[(size_t)(rb + r) * D + d];
        xn_s[r][d] = f;
    }
    __syncthreads();

    const int w = d >> 5, l = d & 31;
    #pragma unroll
    for (int r = w; r < RPB; r += 4) {
        float v0 = xn_s[r][l], v1 = xn_s[r][l + 32];
        float v2 = xn_s[r][l + 64], v3 = xn_s[r][l + 96];
        float s  = v0 + v1 + v2 + v3;
        float sq = v0 * v0 + v1 * v1 + v2 * v2 + v3 * v3;
        #pragma unroll
        for (int o = 16; o; o >>= 1) {
            s  += __shfl_xor_sync(0xffffffffu, s, o);
            sq += __shfl_xor_sync(0xffffffffu, sq, o);
        }
        float m   = s * (1.f / 128.f);
        float var = sq * (1.f / 128.f) - m * m;
        float rs  = rsqrtf(var + 1e-5f);
        size_t base = (size_t)(rb + r) * D;
        out[base + l]      = (v0 - m) * rs * g_out[l]      + b_out[l];
        out[base + l + 32] = (v1 - m) * rs * g_out[l + 32] + b_out[l + 32];
        out[base + l + 64] = (v2 - m) * rs * g_out[l + 64] + b_out[l + 64];
        out[base + l + 96] = (v3 - m) * rs * g_out[l + 96] + b_out[l + 96];
    }
}

// ---------------- launch ----------------
extern "C" void kernel_launch(void* const* d_in, const int* in_sizes, int n_in,
                              void* d_out, int out_size)
{
    (void)in_sizes; (void)n_in; (void)out_size;
    const float* x    = (const float*)d_in[0];
    const float* adj  = (const float*)d_in[1];
    const float* u    = (const float*)d_in[2];
    const float* W1   = (const float*)d_in[3];
    const float* b1   = (const float*)d_in[4];
    const float* W2   = (const float*)d_in[5];
    const float* b2   = (const float*)d_in[6];
    const float* Wg   = (const float*)d_in[7];
    const float* bg   = (const float*)d_in[8];
    const float* Wn   = (const float*)d_in[9];
    const float* bn   = (const float*)d_in[10];
    const float* g_in = (const float*)d_in[11];
    const float* b_in = (const float*)d_in[12];
    const float* g_out= (const float*)d_in[13];
    const float* b_out= (const float*)d_in[14];
    float* out = (float*)d_out;

    reset_kernel<<<1, 1>>>();
    prep_kernel<<<N_ROWS, 128>>>(x, u, Wn, bn, g_in, b_in);
    dim3 g(N_ROWS / TM, KSPLIT);
    gemm_kernel<<<g, 256>>>(adj);
    epilogue_kernel<<<N_ROWS / RPB, 128>>>(x, W1, b1, W2, b2, Wg, bg, g_out, b_out, out);
}